// round 13
// baseline (speedup 1.0000x reference)
#include <cuda_runtime.h>
#include <cuda_fp16.h>
#include <cstdint>

// Problem constants
#define NTOK  8192
#define DIM   1024
#define NE    8
#define MAXK  8
#define SLAB  8320
#define KDIM  1024

// GEMM tiling (fp16, 2 CTAs/SM)
#define BM 128
#define BN 128
#define BK 64
#define KSTEPS (KDIM / BK)   // 16
#define STAGES 3
#define NTHREADS 256
#define ASZ (BM * BK * 2)
#define BSZ (BK * BN * 2)

#define SM_AROW 0
#define SM_ASZT 1024
#define SM_A    2048
#define SM_B    (SM_A + STAGES * ASZ)
#define SMEM_TOTAL (SM_B + STAGES * BSZ)   // 100352 B -> 2 CTAs/SM

#define L_ELEM4 (NE * KDIM * DIM / 4)      // float4s per weight layer (2M)

// ---------------- scratch (device globals) ----------------------------------
__device__ int    g_count[NE];
__device__ int    g_tok  [NE * NTOK];
__device__ float  g_wslot[NE * NTOK];
__device__ __half g_xh  [(size_t)NTOK * DIM];
__device__ __half g_wh  [(size_t)3 * NE * KDIM * DIM];
__device__ __half g_h1h [(size_t)NE * SLAB * DIM];
__device__ __half g_h2h [(size_t)NE * SLAB * DIM];

// ---------------- PTX helpers ------------------------------------------------
__device__ __forceinline__ uint32_t smem_u32(const void* p) {
    uint32_t a;
    asm("{ .reg .u64 t; cvta.to.shared.u64 t, %1; cvt.u32.u64 %0, t; }" : "=r"(a) : "l"(p));
    return a;
}

__device__ __forceinline__ void cp_async16(uint32_t dst, const void* src, uint32_t sz) {
    asm volatile("cp.async.cg.shared.global [%0], [%1], 16, %2;"
                 :: "r"(dst), "l"(src), "r"(sz) : "memory");
}
#define CP_COMMIT() asm volatile("cp.async.commit_group;" ::: "memory")
#define CP_WAIT1()  asm volatile("cp.async.wait_group 1;" ::: "memory")

__device__ __forceinline__ void ldsm4(uint32_t* r, uint32_t addr) {
    asm volatile("ldmatrix.sync.aligned.m8n8.x4.shared.b16 {%0,%1,%2,%3}, [%4];"
                 : "=r"(r[0]), "=r"(r[1]), "=r"(r[2]), "=r"(r[3]) : "r"(addr));
}
__device__ __forceinline__ void ldsm4t(uint32_t* r, uint32_t addr) {
    asm volatile("ldmatrix.sync.aligned.m8n8.x4.trans.shared.b16 {%0,%1,%2,%3}, [%4];"
                 : "=r"(r[0]), "=r"(r[1]), "=r"(r[2]), "=r"(r[3]) : "r"(addr));
}

__device__ __forceinline__ void mma16(float* c, const uint32_t* a, uint32_t b0, uint32_t b1) {
    asm volatile(
        "mma.sync.aligned.m16n8k16.row.col.f32.f16.f16.f32 "
        "{%0,%1,%2,%3}, {%4,%5,%6,%7}, {%8,%9}, {%0,%1,%2,%3};"
        : "+f"(c[0]), "+f"(c[1]), "+f"(c[2]), "+f"(c[3])
        : "r"(a[0]), "r"(a[1]), "r"(a[2]), "r"(a[3]), "r"(b0), "r"(b1));
}

// ---------------- misc helpers -----------------------------------------------
__device__ __forceinline__ int load_topn(const void* p) {
    int v = *(const int*)p;
    if (v >= 1 && v <= MAXK) return v;
    float f = *(const float*)p;
    int vi = (int)(f + 0.5f);
    if (vi >= 1 && vi <= MAXK) return vi;
    return 2;
}

// ---------------- weight f2h (one layer, grid-stride) -------------------------
__global__ void conv_kernel(const float* __restrict__ src,
                            __half* __restrict__ dst) {
    int stride = gridDim.x * blockDim.x;
    for (int j = blockIdx.x * blockDim.x + threadIdx.x; j < L_ELEM4; j += stride) {
        float4 v = ((const float4*)src)[j];
        __half2 h0 = __floats2half2_rn(v.x, v.y);
        __half2 h1 = __floats2half2_rn(v.z, v.w);
        uint32_t u0 = *(uint32_t*)&h0, u1 = *(uint32_t*)&h1;
        ((uint2*)dst)[j] = make_uint2(u0, u1);
    }
}

// ---------------- gating: one warp per token, fully vectorized ---------------
__global__ void gating_kernel(const float* __restrict__ x,
                              const float* __restrict__ gw,
                              const float* __restrict__ gb,
                              const void*  __restrict__ topn_p) {
    int wid  = threadIdx.x >> 5;
    int lane = threadIdx.x & 31;
    int t = blockIdx.x * (blockDim.x >> 5) + wid;
    if (t >= NTOK) return;

    float acc[NE];
#pragma unroll
    for (int e = 0; e < NE; e++) acc[e] = 0.f;

    const float4* xr = (const float4*)(x + (size_t)t * DIM);
    uint2* xo = (uint2*)(g_xh + (size_t)t * DIM);
    const float4* gw4 = (const float4*)gw;            // [DIM][NE] -> 2 float4 per row

#pragma unroll 2
    for (int d4 = lane; d4 < DIM / 4; d4 += 32) {
        float4 xv = xr[d4];
        // fp16 store (4 halves = 8B)
        __half2 h0 = __floats2half2_rn(xv.x, xv.y);
        __half2 h1 = __floats2half2_rn(xv.z, xv.w);
        xo[d4] = make_uint2(*(uint32_t*)&h0, *(uint32_t*)&h1);

        int d = d4 * 4;
        float xs[4] = {xv.x, xv.y, xv.z, xv.w};
#pragma unroll
        for (int i = 0; i < 4; i++) {
            float4 g0 = gw4[(d + i) * 2];
            float4 g1 = gw4[(d + i) * 2 + 1];
            acc[0] += xs[i] * g0.x; acc[1] += xs[i] * g0.y;
            acc[2] += xs[i] * g0.z; acc[3] += xs[i] * g0.w;
            acc[4] += xs[i] * g1.x; acc[5] += xs[i] * g1.y;
            acc[6] += xs[i] * g1.z; acc[7] += xs[i] * g1.w;
        }
    }
#pragma unroll
    for (int e = 0; e < NE; e++) {
        float v = acc[e];
#pragma unroll
        for (int o = 16; o; o >>= 1) v += __shfl_xor_sync(0xffffffffu, v, o);
        acc[e] = v;
    }

    if (lane == 0) {
        float logit[NE];
#pragma unroll
        for (int e = 0; e < NE; e++) logit[e] = acc[e] + gb[e];
        int tn = load_topn(topn_p);

        int sel[MAXK]; float sl[MAXK]; bool used[NE];
#pragma unroll
        for (int e = 0; e < NE; e++) used[e] = false;
        for (int k = 0; k < tn; k++) {
            int best = -1; float bv = -3.4e38f;
#pragma unroll
            for (int e = 0; e < NE; e++)
                if (!used[e] && logit[e] > bv) { bv = logit[e]; best = e; }
            used[best] = true; sel[k] = best; sl[k] = bv;
        }
        float m = sl[0], s = 0.f;
        for (int k = 0; k < tn; k++) { sl[k] = expf(sl[k] - m); s += sl[k]; }
        float inv = 1.f / s;
        for (int k = 0; k < tn; k++) {
            int e = sel[k];
            int slot = atomicAdd(&g_count[e], 1);
            g_tok  [e * NTOK + slot] = t;
            g_wslot[e * NTOK + slot] = sl[k] * inv;
        }
    }
}

// ---------------- grouped GEMM; mode 2 fuses combine --------------------------
__global__ void __launch_bounds__(NTHREADS, 2)
moe_gemm_tc(const __half* __restrict__ W,
            const float* __restrict__ bias,
            float* __restrict__ out,
            int mode) {
    int e = blockIdx.z;
    int cnt = g_count[e];
    int mbase = blockIdx.y * BM;
    if (mbase >= cnt) return;
    int nbase = blockIdx.x * BN;

    extern __shared__ char smem[];
    int tid = threadIdx.x;
    int wid = tid >> 5;
    int lane = tid & 31;
    int g = lane >> 2, tig = lane & 3;

    const __half* Wb = W + (size_t)e * KDIM * DIM;
    const float*  Bb = bias + (size_t)e * DIM;
    const __half* Asrc = (mode == 1) ? g_h1h : g_h2h;

    const __half** Arow = (const __half**)(smem + SM_AROW);
    int* ArowSz = (int*)(smem + SM_ASZT);
    if (tid < BM) {
        int m = mbase + tid;
        const __half* p = g_xh;
        int sz = 0;
        if (m < cnt) {
            sz = 16;
            if (mode == 0) p = g_xh + (size_t)g_tok[e * NTOK + m] * DIM;
            else           p = Asrc + ((size_t)e * SLAB + m) * DIM;
        }
        Arow[tid] = p;
        ArowSz[tid] = sz;
    }
    __syncthreads();

    uint32_t sA = smem_u32(smem + SM_A);
    uint32_t sB = smem_u32(smem + SM_B);

    auto load_stage = [&](int slot, int kt) {
        int k0 = kt * BK;
        uint32_t as = sA + slot * ASZ;
        uint32_t bs = sB + slot * BSZ;
#pragma unroll
        for (int i = 0; i < 4; i++) {
            int idx = tid + i * NTHREADS;
            int r = idx >> 3, ch = idx & 7;
            uint32_t dst = as + r * 128 + ((ch ^ (r & 7)) << 4);
            cp_async16(dst, Arow[r] + k0 + ch * 8, ArowSz[r]);
        }
#pragma unroll
        for (int i = 0; i < 4; i++) {
            int idx = tid + i * NTHREADS;
            int r = idx >> 4, ch = idx & 15;
            uint32_t dst = bs + r * 256 + ((ch ^ (r & 7)) << 4);
            cp_async16(dst, Wb + (size_t)(k0 + r) * DIM + nbase + ch * 8, 16);
        }
    };

    load_stage(0, 0); CP_COMMIT();
    load_stage(1, 1); CP_COMMIT();

    int wm = (wid & 1) * 64;
    int wn = (wid >> 1) * 32;

    int l15 = lane & 15, hi = lane >> 4, l7 = lane & 7;
    uint32_t aRowOff = (uint32_t)(wm + l15) * 128;
    uint32_t swcA[4];
#pragma unroll
    for (int ks = 0; ks < 4; ks++)
        swcA[ks] = (uint32_t)(((ks * 2 + hi) ^ l7) << 4);
    uint32_t bRowOff = (uint32_t)l15 * 256;
    int nch = (wn >> 3);
    uint32_t cBn[2];
#pragma unroll
    for (int nt = 0; nt < 2; nt++)
        cBn[nt] = (uint32_t)((((nch + nt * 2) + hi) ^ l7) << 4);

    float acc[4][4][4];
#pragma unroll
    for (int i = 0; i < 4; i++)
#pragma unroll
        for (int j = 0; j < 4; j++)
#pragma unroll
            for (int q = 0; q < 4; q++) acc[i][j][q] = 0.f;

    int slot = 0;
    for (int kt = 0; kt < KSTEPS; kt++) {
        CP_WAIT1();
        __syncthreads();
        if (kt + 2 < KSTEPS) {
            int ps = slot + 2; if (ps >= STAGES) ps -= STAGES;
            load_stage(ps, kt + 2);
        }
        CP_COMMIT();

        uint32_t as = sA + slot * ASZ + aRowOff;
        uint32_t bs = sB + slot * BSZ + bRowOff;
#pragma unroll
        for (int ks = 0; ks < 4; ks++) {
            uint32_t a[4][4];
#pragma unroll
            for (int mf = 0; mf < 4; mf++)
                ldsm4(a[mf], as + mf * 2048 + swcA[ks]);
            uint32_t b[2][4];
            uint32_t bk = bs + ks * 4096;
            ldsm4t(b[0], bk + cBn[0]);
            ldsm4t(b[1], bk + cBn[1]);
#pragma unroll
            for (int mf = 0; mf < 4; mf++) {
                mma16(acc[mf][0], a[mf], b[0][0], b[0][1]);
                mma16(acc[mf][1], a[mf], b[0][2], b[0][3]);
                mma16(acc[mf][2], a[mf], b[1][0], b[1][1]);
                mma16(acc[mf][3], a[mf], b[1][2], b[1][3]);
            }
        }
        if (++slot == STAGES) slot = 0;
    }

    float bw[4][2];
#pragma unroll
    for (int nf = 0; nf < 4; nf++) {
        int cc = nbase + wn + nf * 8 + 2 * tig;
        bw[nf][0] = Bb[cc];
        bw[nf][1] = Bb[cc + 1];
    }

    if (mode != 2) {
        size_t rowbase = (size_t)e * SLAB + mbase + wm;
        __half* OutH = (mode == 1) ? g_h2h : g_h1h;
#pragma unroll
        for (int mf = 0; mf < 4; mf++) {
            __half* p0 = OutH + (rowbase + mf * 16 + g) * DIM + nbase + wn;
            __half* p1 = p0 + 8 * DIM;
#pragma unroll
            for (int nf = 0; nf < 4; nf++) {
                float v0 = acc[mf][nf][0] + bw[nf][0];
                float v1 = acc[mf][nf][1] + bw[nf][1];
                float v2 = acc[mf][nf][2] + bw[nf][0];
                float v3 = acc[mf][nf][3] + bw[nf][1];
                v0 = (v0 < 0.f) ? 0.01f * v0 : v0;
                v1 = (v1 < 0.f) ? 0.01f * v1 : v1;
                v2 = (v2 < 0.f) ? 0.01f * v2 : v2;
                v3 = (v3 < 0.f) ? 0.01f * v3 : v3;
                int cc = nf * 8 + 2 * tig;
                *(__half2*)(p0 + cc) = __floats2half2_rn(v0, v1);
                *(__half2*)(p1 + cc) = __floats2half2_rn(v2, v3);
            }
        }
    } else {
#pragma unroll
        for (int mf = 0; mf < 4; mf++) {
            int r0 = mbase + wm + mf * 16 + g;
            int r1 = r0 + 8;
            bool ok0 = r0 < cnt, ok1 = r1 < cnt;
            int   t0 = ok0 ? g_tok  [e * NTOK + r0] : 0;
            float w0 = ok0 ? g_wslot[e * NTOK + r0] : 0.f;
            int   t1 = ok1 ? g_tok  [e * NTOK + r1] : 0;
            float w1w = ok1 ? g_wslot[e * NTOK + r1] : 0.f;
            float* o0 = out + (size_t)t0 * DIM + nbase + wn;
            float* o1 = out + (size_t)t1 * DIM + nbase + wn;
#pragma unroll
            for (int nf = 0; nf < 4; nf++) {
                int cc = nf * 8 + 2 * tig;
                if (ok0) {
                    atomicAdd(o0 + cc,     w0 * (acc[mf][nf][0] + bw[nf][0]));
                    atomicAdd(o0 + cc + 1, w0 * (acc[mf][nf][1] + bw[nf][1]));
                }
                if (ok1) {
                    atomicAdd(o1 + cc,     w1w * (acc[mf][nf][2] + bw[nf][0]));
                    atomicAdd(o1 + cc + 1, w1w * (acc[mf][nf][3] + bw[nf][1]));
                }
            }
        }
    }
}

// ---------------- launch ---------------------------------------------------------
extern "C" void kernel_launch(void* const* d_in, const int* in_sizes, int n_in,
                              void* d_out, int out_size) {
    const float* x   = (const float*)d_in[0];
    const float* gw  = (const float*)d_in[1];
    const float* gb  = (const float*)d_in[2];
    const float* w1  = (const float*)d_in[3];
    const float* b1  = (const float*)d_in[4];
    const float* w2  = (const float*)d_in[5];
    const float* b2  = (const float*)d_in[6];
    const float* w3  = (const float*)d_in[7];
    const float* b3  = (const float*)d_in[8];
    const void*  tp  = d_in[9];
    float* out = (float*)d_out;

    static cudaStream_t s1 = nullptr;
    static cudaEvent_t evFork, ev1, ev2, ev3;
    if (!s1) {
        cudaStreamCreateWithFlags(&s1, cudaStreamNonBlocking);
        cudaEventCreateWithFlags(&evFork, cudaEventDisableTiming);
        cudaEventCreateWithFlags(&ev1, cudaEventDisableTiming);
        cudaEventCreateWithFlags(&ev2, cudaEventDisableTiming);
        cudaEventCreateWithFlags(&ev3, cudaEventDisableTiming);
    }

    cudaFuncSetAttribute(moe_gemm_tc, cudaFuncAttributeMaxDynamicSharedMemorySize, SMEM_TOTAL);

    __half *wh;
    int *cnt;
    cudaGetSymbolAddress((void**)&wh, g_wh);
    cudaGetSymbolAddress((void**)&cnt, g_count);
    size_t lsz = (size_t)NE * KDIM * DIM;

    cudaMemsetAsync(cnt, 0, NE * sizeof(int));

    // fork side stream: weight conversions + output zeroing, pipelined per layer
    cudaEventRecord(evFork, 0);
    cudaStreamWaitEvent(s1, evFork, 0);
    conv_kernel<<<2048, 256, 0, s1>>>(w1, wh + 0 * lsz);
    cudaEventRecord(ev1, s1);
    conv_kernel<<<2048, 256, 0, s1>>>(w2, wh + 1 * lsz);
    cudaEventRecord(ev2, s1);
    conv_kernel<<<2048, 256, 0, s1>>>(w3, wh + 2 * lsz);
    cudaMemsetAsync(out, 0, (size_t)NTOK * DIM * sizeof(float), s1);
    cudaEventRecord(ev3, s1);

    // main stream: gating, then GEMMs gated on per-layer weight readiness
    gating_kernel<<<1024, 256>>>(x, gw, gb, tp);

    dim3 grid(DIM / BN, NTOK / BM, NE);    // (8, 64, 8)
    cudaStreamWaitEvent(0, ev1, 0);
    moe_gemm_tc<<<grid, NTHREADS, SMEM_TOTAL>>>(wh + 0 * lsz, b1, out, 0);
    cudaStreamWaitEvent(0, ev2, 0);
    moe_gemm_tc<<<grid, NTHREADS, SMEM_TOTAL>>>(wh + 1 * lsz, b2, out, 1);
    cudaStreamWaitEvent(0, ev3, 0);
    moe_gemm_tc<<<grid, NTHREADS, SMEM_TOTAL>>>(wh + 2 * lsz, b3, out, 2);
}

// round 14
// speedup vs baseline: 1.1122x; 1.1122x over previous
#include <cuda_runtime.h>
#include <cuda_fp16.h>
#include <cstdint>

// Problem constants
#define NTOK  8192
#define DIM   1024
#define NE    8
#define MAXK  8
#define SLAB  8320
#define KDIM  1024

// GEMM tiling (fp16, 2 CTAs/SM)
#define BM 128
#define BN 128
#define BK 64
#define KSTEPS (KDIM / BK)   // 16
#define STAGES 3
#define NTHREADS 256
#define ASZ (BM * BK * 2)
#define BSZ (BK * BN * 2)

#define SM_AROW 0
#define SM_ASZT 1024
#define SM_A    2048
#define SM_B    (SM_A + STAGES * ASZ)
#define SMEM_TOTAL (SM_B + STAGES * BSZ)   // 100352 B -> 2 CTAs/SM

#define L_ELEM4 (NE * KDIM * DIM / 4)      // float4s per weight layer (2M)

// ---------------- scratch (device globals) ----------------------------------
__device__ int    g_count[NE];
__device__ int    g_tok  [NE * NTOK];
__device__ float  g_wslot[NE * NTOK];
__device__ __half g_xh  [(size_t)NTOK * DIM];
__device__ __half g_wh  [(size_t)3 * NE * KDIM * DIM];
__device__ __half g_h1h [(size_t)NE * SLAB * DIM];
__device__ __half g_h2h [(size_t)NE * SLAB * DIM];

// ---------------- PTX helpers ------------------------------------------------
__device__ __forceinline__ uint32_t smem_u32(const void* p) {
    uint32_t a;
    asm("{ .reg .u64 t; cvta.to.shared.u64 t, %1; cvt.u32.u64 %0, t; }" : "=r"(a) : "l"(p));
    return a;
}

__device__ __forceinline__ void cp_async16(uint32_t dst, const void* src, uint32_t sz) {
    asm volatile("cp.async.cg.shared.global [%0], [%1], 16, %2;"
                 :: "r"(dst), "l"(src), "r"(sz) : "memory");
}
#define CP_COMMIT() asm volatile("cp.async.commit_group;" ::: "memory")
#define CP_WAIT1()  asm volatile("cp.async.wait_group 1;" ::: "memory")

__device__ __forceinline__ void ldsm4(uint32_t* r, uint32_t addr) {
    asm volatile("ldmatrix.sync.aligned.m8n8.x4.shared.b16 {%0,%1,%2,%3}, [%4];"
                 : "=r"(r[0]), "=r"(r[1]), "=r"(r[2]), "=r"(r[3]) : "r"(addr));
}
__device__ __forceinline__ void ldsm4t(uint32_t* r, uint32_t addr) {
    asm volatile("ldmatrix.sync.aligned.m8n8.x4.trans.shared.b16 {%0,%1,%2,%3}, [%4];"
                 : "=r"(r[0]), "=r"(r[1]), "=r"(r[2]), "=r"(r[3]) : "r"(addr));
}

__device__ __forceinline__ void mma16(float* c, const uint32_t* a, uint32_t b0, uint32_t b1) {
    asm volatile(
        "mma.sync.aligned.m16n8k16.row.col.f32.f16.f16.f32 "
        "{%0,%1,%2,%3}, {%4,%5,%6,%7}, {%8,%9}, {%0,%1,%2,%3};"
        : "+f"(c[0]), "+f"(c[1]), "+f"(c[2]), "+f"(c[3])
        : "r"(a[0]), "r"(a[1]), "r"(a[2]), "r"(a[3]), "r"(b0), "r"(b1));
}

// ---------------- misc helpers -----------------------------------------------
__device__ __forceinline__ int load_topn(const void* p) {
    int v = *(const int*)p;
    if (v >= 1 && v <= MAXK) return v;
    float f = *(const float*)p;
    int vi = (int)(f + 0.5f);
    if (vi >= 1 && vi <= MAXK) return vi;
    return 2;
}

// ---------------- weight f2h (one layer, grid-stride) -------------------------
__global__ void conv_kernel(const float* __restrict__ src,
                            __half* __restrict__ dst) {
    int stride = gridDim.x * blockDim.x;
    for (int j = blockIdx.x * blockDim.x + threadIdx.x; j < L_ELEM4; j += stride) {
        float4 v = ((const float4*)src)[j];
        __half2 h0 = __floats2half2_rn(v.x, v.y);
        __half2 h1 = __floats2half2_rn(v.z, v.w);
        uint32_t u0 = *(uint32_t*)&h0, u1 = *(uint32_t*)&h1;
        ((uint2*)dst)[j] = make_uint2(u0, u1);
    }
}

// ---------------- gating: one warp per token, coalesced gw -------------------
// gw flat float4 index f4 = it*32+lane covers row d = 16*it + (lane>>1),
// experts 4*(lane&1)..+3. Even lanes accumulate experts 0-3, odd lanes 4-7.
__global__ void gating_kernel(const float* __restrict__ x,
                              const float* __restrict__ gw,
                              const float* __restrict__ gb,
                              const void*  __restrict__ topn_p) {
    int wid  = threadIdx.x >> 5;
    int lane = threadIdx.x & 31;
    int t = blockIdx.x * (blockDim.x >> 5) + wid;
    if (t >= NTOK) return;

    const float4* xr = (const float4*)(x + (size_t)t * DIM);
    uint2* xo = (uint2*)(g_xh + (size_t)t * DIM);

    // phase A: fp16 conversion of x (coalesced)
#pragma unroll
    for (int it = 0; it < 8; it++) {
        int d4 = lane + 32 * it;
        float4 xv = xr[d4];
        __half2 h0 = __floats2half2_rn(xv.x, xv.y);
        __half2 h1 = __floats2half2_rn(xv.z, xv.w);
        xo[d4] = make_uint2(*(uint32_t*)&h0, *(uint32_t*)&h1);
    }

    // phase B: logits with coalesced gw loads
    const float4* gw4 = (const float4*)gw;
    const float* xs = x + (size_t)t * DIM + (lane >> 1);
    float a0 = 0.f, a1 = 0.f, a2 = 0.f, a3 = 0.f;
#pragma unroll 8
    for (int it = 0; it < 64; it++) {
        float4 g4 = gw4[it * 32 + lane];
        float xv = xs[it * 16];
        a0 += xv * g4.x; a1 += xv * g4.y;
        a2 += xv * g4.z; a3 += xv * g4.w;
    }
    // parity-preserving reduction: even lanes sum experts 0-3, odd lanes 4-7
#pragma unroll
    for (int o = 2; o <= 16; o <<= 1) {
        a0 += __shfl_xor_sync(0xffffffffu, a0, o);
        a1 += __shfl_xor_sync(0xffffffffu, a1, o);
        a2 += __shfl_xor_sync(0xffffffffu, a2, o);
        a3 += __shfl_xor_sync(0xffffffffu, a3, o);
    }
    float b0 = __shfl_sync(0xffffffffu, a0, 1);
    float b1 = __shfl_sync(0xffffffffu, a1, 1);
    float b2 = __shfl_sync(0xffffffffu, a2, 1);
    float b3 = __shfl_sync(0xffffffffu, a3, 1);

    if (lane == 0) {
        float logit[NE] = {a0 + gb[0], a1 + gb[1], a2 + gb[2], a3 + gb[3],
                           b0 + gb[4], b1 + gb[5], b2 + gb[6], b3 + gb[7]};
        int tn = load_topn(topn_p);

        int sel[MAXK]; float sl[MAXK]; bool used[NE];
#pragma unroll
        for (int e = 0; e < NE; e++) used[e] = false;
        for (int k = 0; k < tn; k++) {
            int best = -1; float bv = -3.4e38f;
#pragma unroll
            for (int e = 0; e < NE; e++)
                if (!used[e] && logit[e] > bv) { bv = logit[e]; best = e; }
            used[best] = true; sel[k] = best; sl[k] = bv;
        }
        float m = sl[0], s = 0.f;
        for (int k = 0; k < tn; k++) { sl[k] = expf(sl[k] - m); s += sl[k]; }
        float inv = 1.f / s;
        for (int k = 0; k < tn; k++) {
            int e = sel[k];
            int slot = atomicAdd(&g_count[e], 1);
            g_tok  [e * NTOK + slot] = t;
            g_wslot[e * NTOK + slot] = sl[k] * inv;
        }
    }
}

// ---------------- grouped GEMM; mode 2 fuses combine --------------------------
__global__ void __launch_bounds__(NTHREADS, 2)
moe_gemm_tc(const __half* __restrict__ W,
            const float* __restrict__ bias,
            float* __restrict__ out,
            int mode) {
    int e = blockIdx.z;
    int cnt = g_count[e];
    int mbase = blockIdx.y * BM;
    if (mbase >= cnt) return;
    int nbase = blockIdx.x * BN;

    extern __shared__ char smem[];
    int tid = threadIdx.x;
    int wid = tid >> 5;
    int lane = tid & 31;
    int g = lane >> 2, tig = lane & 3;

    const __half* Wb = W + (size_t)e * KDIM * DIM;
    const float*  Bb = bias + (size_t)e * DIM;
    const __half* Asrc = (mode == 1) ? g_h1h : g_h2h;

    const __half** Arow = (const __half**)(smem + SM_AROW);
    int* ArowSz = (int*)(smem + SM_ASZT);
    if (tid < BM) {
        int m = mbase + tid;
        const __half* p = g_xh;
        int sz = 0;
        if (m < cnt) {
            sz = 16;
            if (mode == 0) p = g_xh + (size_t)g_tok[e * NTOK + m] * DIM;
            else           p = Asrc + ((size_t)e * SLAB + m) * DIM;
        }
        Arow[tid] = p;
        ArowSz[tid] = sz;
    }
    __syncthreads();

    uint32_t sA = smem_u32(smem + SM_A);
    uint32_t sB = smem_u32(smem + SM_B);

    auto load_stage = [&](int slot, int kt) {
        int k0 = kt * BK;
        uint32_t as = sA + slot * ASZ;
        uint32_t bs = sB + slot * BSZ;
#pragma unroll
        for (int i = 0; i < 4; i++) {
            int idx = tid + i * NTHREADS;
            int r = idx >> 3, ch = idx & 7;
            uint32_t dst = as + r * 128 + ((ch ^ (r & 7)) << 4);
            cp_async16(dst, Arow[r] + k0 + ch * 8, ArowSz[r]);
        }
#pragma unroll
        for (int i = 0; i < 4; i++) {
            int idx = tid + i * NTHREADS;
            int r = idx >> 4, ch = idx & 15;
            uint32_t dst = bs + r * 256 + ((ch ^ (r & 7)) << 4);
            cp_async16(dst, Wb + (size_t)(k0 + r) * DIM + nbase + ch * 8, 16);
        }
    };

    load_stage(0, 0); CP_COMMIT();
    load_stage(1, 1); CP_COMMIT();

    int wm = (wid & 1) * 64;
    int wn = (wid >> 1) * 32;

    int l15 = lane & 15, hi = lane >> 4, l7 = lane & 7;
    uint32_t aRowOff = (uint32_t)(wm + l15) * 128;
    uint32_t swcA[4];
#pragma unroll
    for (int ks = 0; ks < 4; ks++)
        swcA[ks] = (uint32_t)(((ks * 2 + hi) ^ l7) << 4);
    uint32_t bRowOff = (uint32_t)l15 * 256;
    int nch = (wn >> 3);
    uint32_t cBn[2];
#pragma unroll
    for (int nt = 0; nt < 2; nt++)
        cBn[nt] = (uint32_t)((((nch + nt * 2) + hi) ^ l7) << 4);

    float acc[4][4][4];
#pragma unroll
    for (int i = 0; i < 4; i++)
#pragma unroll
        for (int j = 0; j < 4; j++)
#pragma unroll
            for (int q = 0; q < 4; q++) acc[i][j][q] = 0.f;

    int slot = 0;
    for (int kt = 0; kt < KSTEPS; kt++) {
        CP_WAIT1();
        __syncthreads();
        if (kt + 2 < KSTEPS) {
            int ps = slot + 2; if (ps >= STAGES) ps -= STAGES;
            load_stage(ps, kt + 2);
        }
        CP_COMMIT();

        uint32_t as = sA + slot * ASZ + aRowOff;
        uint32_t bs = sB + slot * BSZ + bRowOff;
#pragma unroll
        for (int ks = 0; ks < 4; ks++) {
            uint32_t a[4][4];
#pragma unroll
            for (int mf = 0; mf < 4; mf++)
                ldsm4(a[mf], as + mf * 2048 + swcA[ks]);
            uint32_t b[2][4];
            uint32_t bk = bs + ks * 4096;
            ldsm4t(b[0], bk + cBn[0]);
            ldsm4t(b[1], bk + cBn[1]);
#pragma unroll
            for (int mf = 0; mf < 4; mf++) {
                mma16(acc[mf][0], a[mf], b[0][0], b[0][1]);
                mma16(acc[mf][1], a[mf], b[0][2], b[0][3]);
                mma16(acc[mf][2], a[mf], b[1][0], b[1][1]);
                mma16(acc[mf][3], a[mf], b[1][2], b[1][3]);
            }
        }
        if (++slot == STAGES) slot = 0;
    }

    float bw[4][2];
#pragma unroll
    for (int nf = 0; nf < 4; nf++) {
        int cc = nbase + wn + nf * 8 + 2 * tig;
        bw[nf][0] = Bb[cc];
        bw[nf][1] = Bb[cc + 1];
    }

    if (mode != 2) {
        size_t rowbase = (size_t)e * SLAB + mbase + wm;
        __half* OutH = (mode == 1) ? g_h2h : g_h1h;
#pragma unroll
        for (int mf = 0; mf < 4; mf++) {
            __half* p0 = OutH + (rowbase + mf * 16 + g) * DIM + nbase + wn;
            __half* p1 = p0 + 8 * DIM;
#pragma unroll
            for (int nf = 0; nf < 4; nf++) {
                float v0 = acc[mf][nf][0] + bw[nf][0];
                float v1 = acc[mf][nf][1] + bw[nf][1];
                float v2 = acc[mf][nf][2] + bw[nf][0];
                float v3 = acc[mf][nf][3] + bw[nf][1];
                v0 = (v0 < 0.f) ? 0.01f * v0 : v0;
                v1 = (v1 < 0.f) ? 0.01f * v1 : v1;
                v2 = (v2 < 0.f) ? 0.01f * v2 : v2;
                v3 = (v3 < 0.f) ? 0.01f * v3 : v3;
                int cc = nf * 8 + 2 * tig;
                *(__half2*)(p0 + cc) = __floats2half2_rn(v0, v1);
                *(__half2*)(p1 + cc) = __floats2half2_rn(v2, v3);
            }
        }
    } else {
#pragma unroll
        for (int mf = 0; mf < 4; mf++) {
            int r0 = mbase + wm + mf * 16 + g;
            int r1 = r0 + 8;
            bool ok0 = r0 < cnt, ok1 = r1 < cnt;
            int   t0 = ok0 ? g_tok  [e * NTOK + r0] : 0;
            float w0 = ok0 ? g_wslot[e * NTOK + r0] : 0.f;
            int   t1 = ok1 ? g_tok  [e * NTOK + r1] : 0;
            float w1w = ok1 ? g_wslot[e * NTOK + r1] : 0.f;
            float* o0 = out + (size_t)t0 * DIM + nbase + wn;
            float* o1 = out + (size_t)t1 * DIM + nbase + wn;
#pragma unroll
            for (int nf = 0; nf < 4; nf++) {
                int cc = nf * 8 + 2 * tig;
                if (ok0) {
                    atomicAdd(o0 + cc,     w0 * (acc[mf][nf][0] + bw[nf][0]));
                    atomicAdd(o0 + cc + 1, w0 * (acc[mf][nf][1] + bw[nf][1]));
                }
                if (ok1) {
                    atomicAdd(o1 + cc,     w1w * (acc[mf][nf][2] + bw[nf][0]));
                    atomicAdd(o1 + cc + 1, w1w * (acc[mf][nf][3] + bw[nf][1]));
                }
            }
        }
    }
}

// ---------------- launch ---------------------------------------------------------
extern "C" void kernel_launch(void* const* d_in, const int* in_sizes, int n_in,
                              void* d_out, int out_size) {
    const float* x   = (const float*)d_in[0];
    const float* gw  = (const float*)d_in[1];
    const float* gb  = (const float*)d_in[2];
    const float* w1  = (const float*)d_in[3];
    const float* b1  = (const float*)d_in[4];
    const float* w2  = (const float*)d_in[5];
    const float* b2  = (const float*)d_in[6];
    const float* w3  = (const float*)d_in[7];
    const float* b3  = (const float*)d_in[8];
    const void*  tp  = d_in[9];
    float* out = (float*)d_out;

    static cudaStream_t s1 = nullptr;
    static cudaEvent_t evFork, ev1, ev2, ev3;
    if (!s1) {
        cudaStreamCreateWithFlags(&s1, cudaStreamNonBlocking);
        cudaEventCreateWithFlags(&evFork, cudaEventDisableTiming);
        cudaEventCreateWithFlags(&ev1, cudaEventDisableTiming);
        cudaEventCreateWithFlags(&ev2, cudaEventDisableTiming);
        cudaEventCreateWithFlags(&ev3, cudaEventDisableTiming);
    }

    cudaFuncSetAttribute(moe_gemm_tc, cudaFuncAttributeMaxDynamicSharedMemorySize, SMEM_TOTAL);

    __half *wh;
    int *cnt;
    cudaGetSymbolAddress((void**)&wh, g_wh);
    cudaGetSymbolAddress((void**)&cnt, g_count);
    size_t lsz = (size_t)NE * KDIM * DIM;

    cudaMemsetAsync(cnt, 0, NE * sizeof(int));

    // fork side stream: weight conversions + output zeroing
    cudaEventRecord(evFork, 0);
    cudaStreamWaitEvent(s1, evFork, 0);
    conv_kernel<<<2048, 256, 0, s1>>>(w1, wh + 0 * lsz);
    cudaEventRecord(ev1, s1);
    conv_kernel<<<2048, 256, 0, s1>>>(w2, wh + 1 * lsz);
    cudaEventRecord(ev2, s1);
    conv_kernel<<<2048, 256, 0, s1>>>(w3, wh + 2 * lsz);
    cudaMemsetAsync(out, 0, (size_t)NTOK * DIM * sizeof(float), s1);
    cudaEventRecord(ev3, s1);

    // main stream: gating, then GEMMs gated on per-layer weight readiness
    gating_kernel<<<1024, 256>>>(x, gw, gb, tp);

    dim3 grid(DIM / BN, NTOK / BM, NE);    // (8, 64, 8)
    cudaStreamWaitEvent(0, ev1, 0);
    moe_gemm_tc<<<grid, NTHREADS, SMEM_TOTAL>>>(wh + 0 * lsz, b1, out, 0);
    cudaStreamWaitEvent(0, ev2, 0);
    moe_gemm_tc<<<grid, NTHREADS, SMEM_TOTAL>>>(wh + 1 * lsz, b2, out, 1);
    cudaStreamWaitEvent(0, ev3, 0);
    moe_gemm_tc<<<grid, NTHREADS, SMEM_TOTAL>>>(wh + 2 * lsz, b3, out, 2);
}